// round 13
// baseline (speedup 1.0000x reference)
#include <cuda_runtime.h>
#include <cuda_bf16.h>
#include <cstdint>

// Problem constants
#define Bc 4
#define Lc 4096
#define Dc 1024
#define Kc 8
#define Mc (Bc*Lc)        // 16384 rows
#define KK2 (2*Dc)        // 2048 GEMM K

// ---------------- device scratch (static, no runtime alloc) ----------------
__device__ float  g_keyf[Bc*2*Lc];                 // [b*2+r][l] fp32 keys
__device__ float  g_rksum[Mc];
__device__ int    g_sidx[Bc*2*Lc];                 // [b*2+r][j] -> original l
__device__ float  g_routed[(size_t)Mc*Dc];         // 64 MB fp32
__device__ __nv_bfloat16 g_A[(size_t)Mc*KK2];      // cat=[x|routed] bf16, 64 MB
__device__ __nv_bfloat16 g_W[(size_t)Dc*KK2];      // w_gate bf16, 4 MB
__device__ __nv_bfloat16 g_z[(size_t)Mc*Dc];       // x·W0 + rksum partial, bf16 32 MB
__device__ float  g_y[(size_t)Mc*Dc];              // pre-LN y, 64 MB

static __device__ __forceinline__ uint32_t pack_bf16(float a, float b) {
    __nv_bfloat162 h = __floats2bfloat162_rn(a, b);
    return *reinterpret_cast<uint32_t*>(&h);
}

// ---------------- K1: route keys (NEON VF4 emulation) + x->bf16 -------------
// (key math must stay EXACT — reference CPU 4-lane interleaved fp32 FMA)
__global__ __launch_bounds__(128) void k_route(const float* __restrict__ x,
                                               const float* __restrict__ wr) {
    __shared__ float sw[2048];
    __shared__ float xs[2][128*17];  // two stages of 128 rows x 16 floats
    const int t = threadIdx.x;       // 0..127
    const int m0 = blockIdx.x * 128;

    #pragma unroll
    for (int i = 0; i < 4; ++i)
        reinterpret_cast<float4*>(sw)[i*128 + t] =
            reinterpret_cast<const float4*>(wr)[i*128 + t];

    float a0[4] = {0.f,0.f,0.f,0.f};
    float a1[4] = {0.f,0.f,0.f,0.f};

    const int lr = t >> 2;           // 0..31
    const int lcq = t & 3;           // 0..3
    float4 v[4];

    #pragma unroll
    for (int p = 0; p < 4; ++p) {
        const int r = p*32 + lr;
        v[p] = reinterpret_cast<const float4*>(x)[(size_t)(m0 + r)*256 + lcq];
        float* d = &xs[0][r*17 + lcq*4];
        d[0] = v[p].x; d[1] = v[p].y; d[2] = v[p].z; d[3] = v[p].w;
        uint2 pk;
        pk.x = pack_bf16(v[p].x, v[p].y);
        pk.y = pack_bf16(v[p].z, v[p].w);
        *reinterpret_cast<uint2*>(g_A + (size_t)(m0 + r)*KK2 + lcq*4) = pk;
    }
    __syncthreads();

    for (int s = 0; s < 64; ++s) {
        const int buf = s & 1;
        if (s < 63) {
            #pragma unroll
            for (int p = 0; p < 4; ++p)
                v[p] = reinterpret_cast<const float4*>(x)
                           [(size_t)(m0 + p*32 + lr)*256 + (s + 1)*4 + lcq];
        }
        {
            const float* row = &xs[buf][t*17];
            const int kb = s*16;
            #pragma unroll
            for (int k = 0; k < 16; ++k) {
                const float xv = row[k];
                const int lane = k & 3;
                a0[lane] = fmaf(xv, sw[kb + k],        a0[lane]);
                a1[lane] = fmaf(xv, sw[1024 + kb + k], a1[lane]);
            }
        }
        if (s < 63) {
            #pragma unroll
            for (int p = 0; p < 4; ++p) {
                const int r = p*32 + lr;
                float* d = &xs[buf ^ 1][r*17 + lcq*4];
                d[0] = v[p].x; d[1] = v[p].y; d[2] = v[p].z; d[3] = v[p].w;
                uint2 pk;
                pk.x = pack_bf16(v[p].x, v[p].y);
                pk.y = pack_bf16(v[p].z, v[p].w);
                *reinterpret_cast<uint2*>(g_A + (size_t)(m0 + r)*KK2 + (s+1)*16 + lcq*4) = pk;
            }
        }
        __syncthreads();
    }

    const float k0 = (a0[0] + a0[1]) + (a0[2] + a0[3]);
    const float k1 = (a1[0] + a1[1]) + (a1[2] + a1[3]);
    const int m = m0 + t;
    const int b = m >> 12, l = m & 4095;
    g_keyf[(b*2 + 0)*Lc + l] = k0;
    g_keyf[(b*2 + 1)*Lc + l] = k1;
    g_rksum[m] = k0 + k1;
}

// ---------------- K1c: w_gate -> bf16 ---------------------------------------
__global__ __launch_bounds__(256) void k_wcvt(const float* __restrict__ w) {
    const int gi = blockIdx.x * 256 + threadIdx.x;      // over Dc*KK2/4 float4s
    const float4 v = reinterpret_cast<const float4*>(w)[gi];
    uint2 pk;
    pk.x = pack_bf16(v.x, v.y);
    pk.y = pack_bf16(v.z, v.w);
    reinterpret_cast<uint2*>(g_W)[gi] = pk;
}

// ---------------- K2: STABLE bitonic argsort per (b,r) ----------------------
__global__ void k_sort() {
    const int r = blockIdx.x, b = blockIdx.y;
    const int tid = threadIdx.x;                 // 0..1023
    __shared__ unsigned long long s[Lc];
    const float* keys = g_keyf + (size_t)(b*2 + r)*Lc;
    for (int i = tid; i < Lc; i += 1024) {
        unsigned u = __float_as_uint(keys[i]);
        u = (u & 0x80000000u) ? ~u : (u | 0x80000000u);
        s[i] = ((unsigned long long)u << 32) | (unsigned)i;
    }
    __syncthreads();
    for (int size = 2; size <= Lc; size <<= 1) {
        for (int stride = size >> 1; stride > 0; stride >>= 1) {
            #pragma unroll 2
            for (int t = tid; t < Lc/2; t += 1024) {
                const int i = 2*t - (t & (stride - 1));
                const int j = i + stride;
                const bool up = ((i & size) == 0);
                unsigned long long a = s[i], c = s[j];
                if ((a > c) == up) { s[i] = c; s[j] = a; }
            }
            __syncthreads();
        }
    }
    for (int i = tid; i < Lc; i += 1024)
        g_sidx[(size_t)(b*2 + r)*Lc + i] = (int)(s[i] & 0xffffffffu);
}

// ---------------- K3: conv via register sliding window + scatter -----------
template <int PASS>
__global__ __launch_bounds__(256) void k_conv(const float* __restrict__ x,
                                              const float* __restrict__ convw) {
    const int jt = blockIdx.x;          // 0..63  (64 outputs each)
    const int dc = blockIdx.y;          // 0..3
    const int b  = blockIdx.z;          // 0..3
    const int t  = threadIdx.x;         // 0..255
    const int dbase = dc * 256;
    const int j0 = jt * 64;
    const int* __restrict__ sidx = g_sidx + (size_t)(b*2 + PASS)*Lc;

    __shared__ int sl[72];              // rows j0-4 .. j0+67
    if (t < 72) {
        const int p = j0 - 4 + t;
        sl[t] = (p >= 0 && p < Lc) ? sidx[p] : -1;
    }
    __syncthreads();

    float w[Kc];
    #pragma unroll
    for (int k = 0; k < Kc; ++k) w[k] = convw[(size_t)(dbase + t)*Kc + k];

    const float* __restrict__ xb = x + (size_t)b*Lc*Dc + dbase + t;

    float r[8];
    #pragma unroll
    for (int i = 0; i < 8; ++i) {
        const int s = sl[i];
        r[i] = (s >= 0) ? __ldg(xb + (size_t)s*Dc) : 0.f;
    }

    for (int jj = 0; jj < 64; jj += 4) {
        float nv[4];
        #pragma unroll
        for (int u = 0; u < 4; ++u) {
            const int s = sl[jj + 8 + u];
            nv[u] = (s >= 0) ? __ldg(xb + (size_t)s*Dc) : 0.f;
        }
        #pragma unroll
        for (int u = 0; u < 4; ++u) {
            float acc = r[0] * w[0];
            #pragma unroll
            for (int k = 1; k < 8; ++k) acc = fmaf(r[k], w[k], acc);
            const int l = sl[jj + u + 4];       // always valid
            const size_t off = ((size_t)(b*Lc + l))*Dc + dbase + t;
            if (PASS == 0) {
                g_routed[off] = acc;
            } else {
                const float tot = (g_routed[off] + acc) * 0.5f;   // /R
                g_routed[off] = tot;
                g_A[((size_t)(b*Lc + l))*KK2 + Dc + dbase + t] = __float2bfloat16(tot);
            }
            #pragma unroll
            for (int k = 0; k < 7; ++k) r[k] = r[k+1];
            r[7] = nv[u];
        }
    }
}

// ====== K4: split bf16 mma.sync GEMM, 4-stage single-sync, 2 CTA/SM =========
// (R10-proven configuration: 128x128 CTA tile, 64x32 warp tile)
// PHASE 0: g_z = bf16(x·W0 + rksum)   (runs concurrent with sort/conv)
// PHASE 1: y = x + sigmoid(g_z + routed·W1) * routed
#define GP 40                  // smem pitch in bf16
#define STGB (128*GP*2)        // one 128x32 bf16 tile = 10240 B
#define GSTG (2*STGB)          // A+B per stage = 20480 B
#define NST 4                  // pipeline stages
#define GSMEM (NST*GSTG)       // 81920 B; 2 CTAs/SM = 160 KB
#define NIT 32                 // K=1024 per phase, 32 bf16 per iter

static __device__ __forceinline__ uint32_t s2u(const void* p) {
    uint32_t a;
    asm("{ .reg .u64 t; cvta.to.shared.u64 t, %1; cvt.u32.u64 %0, t; }"
        : "=r"(a) : "l"(p));
    return a;
}
static __device__ __forceinline__ void cp16(uint32_t s, const void* g) {
    asm volatile("cp.async.cg.shared.global [%0], [%1], 16;" :: "r"(s), "l"(g));
}
#define CP_COMMIT() asm volatile("cp.async.commit_group;" ::: "memory")
template <int N>
static __device__ __forceinline__ void cp_wait() {
    asm volatile("cp.async.wait_group %0;" :: "n"(N) : "memory");
}
static __device__ __forceinline__ void ldsm4(uint32_t& r0, uint32_t& r1,
                                             uint32_t& r2, uint32_t& r3, uint32_t a) {
    asm volatile("ldmatrix.sync.aligned.m8n8.x4.shared.b16 {%0,%1,%2,%3}, [%4];"
                 : "=r"(r0), "=r"(r1), "=r"(r2), "=r"(r3) : "r"(a));
}

template <int PHASE>
__global__ __launch_bounds__(256, 2) void k_gemm(const float* __restrict__ x) {
    extern __shared__ char smem[];
    const uint32_t sbase = s2u(smem);
    const int tid = threadIdx.x;
    const int n0 = blockIdx.x * 128, m0 = blockIdx.y * 128;

    const int w = tid >> 5, lane = tid & 31;
    const int wm = w >> 2, wn = w & 3;       // 2x4 warp grid, 64x32 warp tile
    const int grp = lane >> 2, q = lane & 3;

    const int ldr  = (tid) >> 2;             // rows 0..63
    const int ldr2 = (tid + 256) >> 2;       // rows 64..127
    const int lcb  = (tid & 3) * 16;         // byte col 0/16/32/48
    const char* Ag = (const char*)(g_A + (size_t)m0 * KK2 + PHASE*Dc);
    const char* Bg = (const char*)(g_W + (size_t)n0 * KK2 + PHASE*Dc);

    const uint32_t aLoff = (uint32_t)((lane & 15) * (GP*2) + ((lane >> 4) * 8) * 2);
    const uint32_t bLoff = (uint32_t)(((lane & 7) + ((lane >> 4) & 1) * 8) * (GP*2)
                                      + (((lane >> 3) & 1) * 8) * 2);

    float acc[4][4][4];
    #pragma unroll
    for (int a = 0; a < 4; ++a)
        #pragma unroll
        for (int bn = 0; bn < 4; ++bn)
            #pragma unroll
            for (int c = 0; c < 4; ++c) acc[a][bn][c] = 0.f;

    auto stage_load = [&](int stg, int kt) {
        const uint32_t as = sbase + stg*GSTG;
        const uint32_t bs = as + STGB;
        const size_t gk = (size_t)kt * 64;   // byte offset of k-tile (32 bf16)
        cp16(as + ldr *80 + lcb, Ag + (size_t)ldr *(KK2*2) + gk + lcb);
        cp16(as + ldr2*80 + lcb, Ag + (size_t)ldr2*(KK2*2) + gk + lcb);
        cp16(bs + ldr *80 + lcb, Bg + (size_t)ldr *(KK2*2) + gk + lcb);
        cp16(bs + ldr2*80 + lcb, Bg + (size_t)ldr2*(KK2*2) + gk + lcb);
    };

    // prologue: loads for iters 0..NST-2
    #pragma unroll
    for (int s = 0; s < NST-1; ++s) { stage_load(s, s); CP_COMMIT(); }

    for (int it = 0; it < NIT; ++it) {
        cp_wait<NST-2>();
        __syncthreads();     // single barrier per iteration

        const int slot = it & (NST-1);
        const uint32_t as = sbase + slot*GSTG;
        const uint32_t bs = as + STGB;

        // ks=0 fragments first (so the cp.async below can't clobber anything live)
        uint32_t af[4][4], bf[4][2];
        #pragma unroll
        for (int mt = 0; mt < 4; ++mt)
            ldsm4(af[mt][0], af[mt][1], af[mt][2], af[mt][3],
                  as + (uint32_t)((wm*64 + mt*16)*(GP*2)) + aLoff);
        #pragma unroll
        for (int p2 = 0; p2 < 2; ++p2)
            ldsm4(bf[p2*2][0], bf[p2*2][1], bf[p2*2+1][0], bf[p2*2+1][1],
                  bs + (uint32_t)((wn*32 + p2*16)*(GP*2)) + bLoff);

        // issue load for iter it+NST-1 into slot (it-1)%NST (consumed last iter)
        if (it + NST-1 < NIT) stage_load((it + NST-1) & (NST-1), it + NST-1);
        CP_COMMIT();   // empty groups in tail keep wait-count semantics

        #pragma unroll
        for (int mt = 0; mt < 4; ++mt)
            #pragma unroll
            for (int nt = 0; nt < 4; ++nt)
                asm volatile(
                    "mma.sync.aligned.m16n8k16.row.col.f32.bf16.bf16.f32 "
                    "{%0,%1,%2,%3}, {%4,%5,%6,%7}, {%8,%9}, {%0,%1,%2,%3};"
                    : "+f"(acc[mt][nt][0]), "+f"(acc[mt][nt][1]),
                      "+f"(acc[mt][nt][2]), "+f"(acc[mt][nt][3])
                    : "r"(af[mt][0]), "r"(af[mt][1]), "r"(af[mt][2]), "r"(af[mt][3]),
                      "r"(bf[nt][0]), "r"(bf[nt][1]));

        // ks=1
        #pragma unroll
        for (int mt = 0; mt < 4; ++mt)
            ldsm4(af[mt][0], af[mt][1], af[mt][2], af[mt][3],
                  as + (uint32_t)((wm*64 + mt*16)*(GP*2) + 32) + aLoff);
        #pragma unroll
        for (int p2 = 0; p2 < 2; ++p2)
            ldsm4(bf[p2*2][0], bf[p2*2][1], bf[p2*2+1][0], bf[p2*2+1][1],
                  bs + (uint32_t)((wn*32 + p2*16)*(GP*2) + 32) + bLoff);
        #pragma unroll
        for (int mt = 0; mt < 4; ++mt)
            #pragma unroll
            for (int nt = 0; nt < 4; ++nt)
                asm volatile(
                    "mma.sync.aligned.m16n8k16.row.col.f32.bf16.bf16.f32 "
                    "{%0,%1,%2,%3}, {%4,%5,%6,%7}, {%8,%9}, {%0,%1,%2,%3};"
                    : "+f"(acc[mt][nt][0]), "+f"(acc[mt][nt][1]),
                      "+f"(acc[mt][nt][2]), "+f"(acc[mt][nt][3])
                    : "r"(af[mt][0]), "r"(af[mt][1]), "r"(af[mt][2]), "r"(af[mt][3]),
                      "r"(bf[nt][0]), "r"(bf[nt][1]));
    }

    // epilogue
    #pragma unroll
    for (int mt = 0; mt < 4; ++mt) {
        const int gm0 = m0 + wm*64 + mt*16 + grp;
        float rks0 = 0.f, rks1 = 0.f;
        if (PHASE == 0) { rks0 = g_rksum[gm0]; rks1 = g_rksum[gm0 + 8]; }
        #pragma unroll
        for (int nt = 0; nt < 4; ++nt) {
            const int gn = n0 + wn*32 + nt*8 + q*2;
            #pragma unroll
            for (int hh = 0; hh < 2; ++hh) {
                const int gm = gm0 + hh*8;
                const float rks = hh ? rks1 : rks0;
                const float c0 = acc[mt][nt][hh*2 + 0];
                const float c1 = acc[mt][nt][hh*2 + 1];
                const size_t o = (size_t)gm*Dc + gn;
                if (PHASE == 0) {
                    *reinterpret_cast<uint32_t*>(g_z + o) =
                        pack_bf16(c0 + rks, c1 + rks);
                } else {
                    const __nv_bfloat162 zh =
                        *reinterpret_cast<const __nv_bfloat162*>(g_z + o);
                    const float g0 = 1.f / (1.f + __expf(-(c0 + __bfloat162float(zh.x))));
                    const float g1 = 1.f / (1.f + __expf(-(c1 + __bfloat162float(zh.y))));
                    const float2 xv = *reinterpret_cast<const float2*>(x + o);
                    const float2 rv = *reinterpret_cast<const float2*>(g_routed + o);
                    float2 yv;
                    yv.x = xv.x + g0*rv.x;
                    yv.y = xv.y + g1*rv.y;
                    *reinterpret_cast<float2*>(g_y + o) = yv;
                }
            }
        }
    }
}

// ---------------- K5: LayerNorm over D ---------------------------------------
__global__ void k_ln(float* __restrict__ out, const float* __restrict__ gamma,
                     const float* __restrict__ beta) {
    const int m = blockIdx.x, t = threadIdx.x;     // 256 threads, 4 floats each
    const float4 v = reinterpret_cast<const float4*>(g_y + (size_t)m*Dc)[t];
    const int lane = t & 31, wid = t >> 5;
    __shared__ float red[16];

    float s = v.x + v.y + v.z + v.w;
    #pragma unroll
    for (int o = 16; o; o >>= 1) s += __shfl_xor_sync(0xffffffffu, s, o);
    if (lane == 0) red[wid] = s;
    __syncthreads();
    float mu = 0.f;
    #pragma unroll
    for (int i = 0; i < 8; ++i) mu += red[i];
    mu *= (1.f / Dc);

    const float d0 = v.x - mu, d1 = v.y - mu, d2 = v.z - mu, d3 = v.w - mu;
    float ss = d0*d0 + d1*d1 + d2*d2 + d3*d3;
    #pragma unroll
    for (int o = 16; o; o >>= 1) ss += __shfl_xor_sync(0xffffffffu, ss, o);
    if (lane == 0) red[8 + wid] = ss;
    __syncthreads();
    float var = 0.f;
    #pragma unroll
    for (int i = 0; i < 8; ++i) var += red[8 + i];
    var *= (1.f / Dc);
    const float inv = rsqrtf(var + 1e-5f);

    const float4 gm = reinterpret_cast<const float4*>(gamma)[t];
    const float4 bt = reinterpret_cast<const float4*>(beta)[t];
    float4 o4;
    o4.x = d0 * inv * gm.x + bt.x;
    o4.y = d1 * inv * gm.y + bt.y;
    o4.z = d2 * inv * gm.z + bt.z;
    o4.w = d3 * inv * gm.w + bt.w;
    reinterpret_cast<float4*>(out + (size_t)m*Dc)[t] = o4;
}

// ---------------- launch ------------------------------------------------------
extern "C" void kernel_launch(void* const* d_in, const int* in_sizes, int n_in,
                              void* d_out, int out_size) {
    const float* x        = (const float*)d_in[0];
    const float* w_route  = (const float*)d_in[1];
    const float* conv_w0  = (const float*)d_in[2];
    const float* conv_w1  = (const float*)d_in[3];
    const float* w_gate   = (const float*)d_in[4];
    const float* ln_gamma = (const float*)d_in[5];
    const float* ln_beta  = (const float*)d_in[6];
    float* out = (float*)d_out;

    static cudaStream_t s1 = nullptr, s2 = nullptr;
    static cudaEvent_t eFork0 = nullptr, eFork = nullptr, eJoin = nullptr, eW = nullptr;
    if (s1 == nullptr) {
        cudaStreamCreateWithFlags(&s1, cudaStreamNonBlocking);
        cudaStreamCreateWithFlags(&s2, cudaStreamNonBlocking);
        cudaEventCreateWithFlags(&eFork0, cudaEventDisableTiming);
        cudaEventCreateWithFlags(&eFork,  cudaEventDisableTiming);
        cudaEventCreateWithFlags(&eJoin,  cudaEventDisableTiming);
        cudaEventCreateWithFlags(&eW,     cudaEventDisableTiming);
        cudaFuncSetAttribute(k_gemm<0>, cudaFuncAttributeMaxDynamicSharedMemorySize, GSMEM);
        cudaFuncSetAttribute(k_gemm<1>, cudaFuncAttributeMaxDynamicSharedMemorySize, GSMEM);
    }

    // legal capture fork for s2: fork from stream 0 BEFORE launching on s2
    cudaEventRecord(eFork0, 0);
    cudaStreamWaitEvent(s2, eFork0, 0);
    k_wcvt<<<(Dc*(KK2/4))/256, 256, 0, s2>>>(w_gate);   // overlaps with k_route
    cudaEventRecord(eW, s2);

    k_route<<<Mc/128, 128>>>(x, w_route);

    // fork: sort + conv chain on side stream, overlapped with GEMM phase 0
    cudaEventRecord(eFork, 0);
    cudaStreamWaitEvent(s1, eFork, 0);
    k_sort<<<dim3(2, Bc), 1024, 0, s1>>>();
    k_conv<0><<<dim3(Lc/64, Dc/256, Bc), 256, 0, s1>>>(x, conv_w0);
    k_conv<1><<<dim3(Lc/64, Dc/256, Bc), 256, 0, s1>>>(x, conv_w1);
    cudaEventRecord(eJoin, s1);

    // gemm0 needs g_A left half (route, same stream) + g_W (wcvt on s2)
    cudaStreamWaitEvent(0, eW, 0);
    k_gemm<0><<<dim3(Dc/128, Mc/128), 256, GSMEM>>>(x);

    // join, then phase 1 + LN
    cudaStreamWaitEvent(0, eJoin, 0);
    k_gemm<1><<<dim3(Dc/128, Mc/128), 256, GSMEM>>>(x);
    k_ln<<<Mc, 256>>>(out, ln_gamma, ln_beta);
}

// round 14
// speedup vs baseline: 1.3393x; 1.3393x over previous
#include <cuda_runtime.h>
#include <cuda_bf16.h>
#include <cstdint>

// Problem constants
#define Bc 4
#define Lc 4096
#define Dc 1024
#define Kc 8
#define Mc (Bc*Lc)        // 16384 rows
#define KK2 (2*Dc)        // 2048 GEMM K

// ---------------- device scratch (static, no runtime alloc) ----------------
__device__ float  g_keyf[Bc*2*Lc];                 // [b*2+r][l] fp32 keys
__device__ float  g_rksum[Mc];
__device__ int    g_sidx[Bc*2*Lc];                 // [b*2+r][j] -> original l
__device__ float  g_routed[(size_t)Mc*Dc];         // 64 MB fp32
__device__ __nv_bfloat16 g_A[(size_t)Mc*KK2];      // cat=[x|routed] bf16, 64 MB
__device__ __nv_bfloat16 g_W[(size_t)Dc*KK2];      // w_gate bf16, 4 MB
__device__ __nv_bfloat16 g_z[(size_t)Mc*Dc];       // x·W0 + rksum partial, bf16 32 MB
__device__ float  g_y[(size_t)Mc*Dc];              // pre-LN y, 64 MB

static __device__ __forceinline__ uint32_t pack_bf16(float a, float b) {
    __nv_bfloat162 h = __floats2bfloat162_rn(a, b);
    return *reinterpret_cast<uint32_t*>(&h);
}

// ---------------- K1: route keys (NEON VF4 emulation) + x->bf16 -------------
// (key math must stay EXACT — reference CPU 4-lane interleaved fp32 FMA.
//  256 threads: all stage loads, threads 0..127 compute rows — per-row FMA
//  sequence is bit-identical to the proven version.)
__global__ __launch_bounds__(256) void k_route(const float* __restrict__ x,
                                               const float* __restrict__ wr) {
    __shared__ float sw[2048];
    __shared__ float xs[2][128*17];  // two stages of 128 rows x 16 floats
    const int t = threadIdx.x;       // 0..255
    const int m0 = blockIdx.x * 128;

    reinterpret_cast<float4*>(sw)[t]       = reinterpret_cast<const float4*>(wr)[t];
    reinterpret_cast<float4*>(sw)[256 + t] = reinterpret_cast<const float4*>(wr)[256 + t];

    float a0[4] = {0.f,0.f,0.f,0.f};
    float a1[4] = {0.f,0.f,0.f,0.f};

    // loader mapping: idx = p*256 + t; row = idx>>2 (0..127); lcq = idx&3
    float4 v[2];

    // prologue: stage 0 load + store + bf16 write
    #pragma unroll
    for (int p = 0; p < 2; ++p) {
        const int idx = p*256 + t;
        const int r = idx >> 2, lcq = idx & 3;
        v[p] = reinterpret_cast<const float4*>(x)[(size_t)(m0 + r)*256 + lcq];
        float* d = &xs[0][r*17 + lcq*4];
        d[0] = v[p].x; d[1] = v[p].y; d[2] = v[p].z; d[3] = v[p].w;
        uint2 pk;
        pk.x = pack_bf16(v[p].x, v[p].y);
        pk.y = pack_bf16(v[p].z, v[p].w);
        *reinterpret_cast<uint2*>(g_A + (size_t)(m0 + r)*KK2 + lcq*4) = pk;
    }
    __syncthreads();

    for (int s = 0; s < 64; ++s) {
        const int buf = s & 1;
        if (s < 63) {
            #pragma unroll
            for (int p = 0; p < 2; ++p) {
                const int idx = p*256 + t;
                const int r = idx >> 2, lcq = idx & 3;
                v[p] = reinterpret_cast<const float4*>(x)
                           [(size_t)(m0 + r)*256 + (s + 1)*4 + lcq];
            }
        }
        // compute stage s (rows owned by threads 0..127; order identical)
        if (t < 128) {
            const float* row = &xs[buf][t*17];
            const int kb = s*16;
            #pragma unroll
            for (int k = 0; k < 16; ++k) {
                const float xv = row[k];
                const int lane = k & 3;
                a0[lane] = fmaf(xv, sw[kb + k],        a0[lane]);
                a1[lane] = fmaf(xv, sw[1024 + kb + k], a1[lane]);
            }
        }
        if (s < 63) {
            #pragma unroll
            for (int p = 0; p < 2; ++p) {
                const int idx = p*256 + t;
                const int r = idx >> 2, lcq = idx & 3;
                float* d = &xs[buf ^ 1][r*17 + lcq*4];
                d[0] = v[p].x; d[1] = v[p].y; d[2] = v[p].z; d[3] = v[p].w;
                uint2 pk;
                pk.x = pack_bf16(v[p].x, v[p].y);
                pk.y = pack_bf16(v[p].z, v[p].w);
                *reinterpret_cast<uint2*>(g_A + (size_t)(m0 + r)*KK2 + (s+1)*16 + lcq*4) = pk;
            }
        }
        __syncthreads();
    }

    if (t < 128) {
        const float k0 = (a0[0] + a0[1]) + (a0[2] + a0[3]);
        const float k1 = (a1[0] + a1[1]) + (a1[2] + a1[3]);
        const int m = m0 + t;
        const int b = m >> 12, l = m & 4095;
        g_keyf[(b*2 + 0)*Lc + l] = k0;
        g_keyf[(b*2 + 1)*Lc + l] = k1;
        g_rksum[m] = k0 + k1;
    }
}

// ---------------- K1c: w_gate -> bf16 ---------------------------------------
__global__ __launch_bounds__(256) void k_wcvt(const float* __restrict__ w) {
    const int gi = blockIdx.x * 256 + threadIdx.x;      // over Dc*KK2/4 float4s
    const float4 v = reinterpret_cast<const float4*>(w)[gi];
    uint2 pk;
    pk.x = pack_bf16(v.x, v.y);
    pk.y = pack_bf16(v.z, v.w);
    reinterpret_cast<uint2*>(g_W)[gi] = pk;
}

// ---------------- K2: STABLE bitonic argsort per (b,r) ----------------------
__global__ void k_sort() {
    const int r = blockIdx.x, b = blockIdx.y;
    const int tid = threadIdx.x;                 // 0..1023
    __shared__ unsigned long long s[Lc];
    const float* keys = g_keyf + (size_t)(b*2 + r)*Lc;
    for (int i = tid; i < Lc; i += 1024) {
        unsigned u = __float_as_uint(keys[i]);
        u = (u & 0x80000000u) ? ~u : (u | 0x80000000u);
        s[i] = ((unsigned long long)u << 32) | (unsigned)i;
    }
    __syncthreads();
    for (int size = 2; size <= Lc; size <<= 1) {
        for (int stride = size >> 1; stride > 0; stride >>= 1) {
            #pragma unroll 2
            for (int t = tid; t < Lc/2; t += 1024) {
                const int i = 2*t - (t & (stride - 1));
                const int j = i + stride;
                const bool up = ((i & size) == 0);
                unsigned long long a = s[i], c = s[j];
                if ((a > c) == up) { s[i] = c; s[j] = a; }
            }
            __syncthreads();
        }
    }
    for (int i = tid; i < Lc; i += 1024)
        g_sidx[(size_t)(b*2 + r)*Lc + i] = (int)(s[i] & 0xffffffffu);
}

// ---------------- K3: conv via register sliding window + scatter -----------
template <int PASS>
__global__ __launch_bounds__(256) void k_conv(const float* __restrict__ x,
                                              const float* __restrict__ convw) {
    const int jt = blockIdx.x;          // 0..63  (64 outputs each)
    const int dc = blockIdx.y;          // 0..3
    const int b  = blockIdx.z;          // 0..3
    const int t  = threadIdx.x;         // 0..255
    const int dbase = dc * 256;
    const int j0 = jt * 64;
    const int* __restrict__ sidx = g_sidx + (size_t)(b*2 + PASS)*Lc;

    __shared__ int sl[72];              // rows j0-4 .. j0+67
    if (t < 72) {
        const int p = j0 - 4 + t;
        sl[t] = (p >= 0 && p < Lc) ? sidx[p] : -1;
    }
    __syncthreads();

    float w[Kc];
    #pragma unroll
    for (int k = 0; k < Kc; ++k) w[k] = convw[(size_t)(dbase + t)*Kc + k];

    const float* __restrict__ xb = x + (size_t)b*Lc*Dc + dbase + t;

    float r[8];
    #pragma unroll
    for (int i = 0; i < 8; ++i) {
        const int s = sl[i];
        r[i] = (s >= 0) ? __ldg(xb + (size_t)s*Dc) : 0.f;
    }

    for (int jj = 0; jj < 64; jj += 4) {
        float nv[4];
        #pragma unroll
        for (int u = 0; u < 4; ++u) {
            const int s = sl[jj + 8 + u];
            nv[u] = (s >= 0) ? __ldg(xb + (size_t)s*Dc) : 0.f;
        }
        #pragma unroll
        for (int u = 0; u < 4; ++u) {
            float acc = r[0] * w[0];
            #pragma unroll
            for (int k = 1; k < 8; ++k) acc = fmaf(r[k], w[k], acc);
            const int l = sl[jj + u + 4];       // always valid
            const size_t off = ((size_t)(b*Lc + l))*Dc + dbase + t;
            if (PASS == 0) {
                g_routed[off] = acc;
            } else {
                const float tot = (g_routed[off] + acc) * 0.5f;   // /R
                g_routed[off] = tot;
                g_A[((size_t)(b*Lc + l))*KK2 + Dc + dbase + t] = __float2bfloat16(tot);
            }
            #pragma unroll
            for (int k = 0; k < 7; ++k) r[k] = r[k+1];
            r[7] = nv[u];
        }
    }
}

// ====== K4: split bf16 mma.sync GEMM, 4-stage single-sync, 2 CTA/SM =========
// (R10-proven configuration: 128x128 CTA tile, 64x32 warp tile)
// PHASE 0: g_z = bf16(x·W0 + rksum)   (runs concurrent with sort/conv)
// PHASE 1: y = x + sigmoid(g_z + routed·W1) * routed
#define GP 40                  // smem pitch in bf16
#define STGB (128*GP*2)        // one 128x32 bf16 tile = 10240 B
#define GSTG (2*STGB)          // A+B per stage = 20480 B
#define NST 4                  // pipeline stages
#define GSMEM (NST*GSTG)       // 81920 B; 2 CTAs/SM = 160 KB
#define NIT 32                 // K=1024 per phase, 32 bf16 per iter

static __device__ __forceinline__ uint32_t s2u(const void* p) {
    uint32_t a;
    asm("{ .reg .u64 t; cvta.to.shared.u64 t, %1; cvt.u32.u64 %0, t; }"
        : "=r"(a) : "l"(p));
    return a;
}
static __device__ __forceinline__ void cp16(uint32_t s, const void* g) {
    asm volatile("cp.async.cg.shared.global [%0], [%1], 16;" :: "r"(s), "l"(g));
}
#define CP_COMMIT() asm volatile("cp.async.commit_group;" ::: "memory")
template <int N>
static __device__ __forceinline__ void cp_wait() {
    asm volatile("cp.async.wait_group %0;" :: "n"(N) : "memory");
}
static __device__ __forceinline__ void ldsm4(uint32_t& r0, uint32_t& r1,
                                             uint32_t& r2, uint32_t& r3, uint32_t a) {
    asm volatile("ldmatrix.sync.aligned.m8n8.x4.shared.b16 {%0,%1,%2,%3}, [%4];"
                 : "=r"(r0), "=r"(r1), "=r"(r2), "=r"(r3) : "r"(a));
}

template <int PHASE>
__global__ __launch_bounds__(256, 2) void k_gemm(const float* __restrict__ x) {
    extern __shared__ char smem[];
    const uint32_t sbase = s2u(smem);
    const int tid = threadIdx.x;
    const int n0 = blockIdx.x * 128, m0 = blockIdx.y * 128;

    const int w = tid >> 5, lane = tid & 31;
    const int wm = w >> 2, wn = w & 3;       // 2x4 warp grid, 64x32 warp tile
    const int grp = lane >> 2, q = lane & 3;

    const int ldr  = (tid) >> 2;             // rows 0..63
    const int ldr2 = (tid + 256) >> 2;       // rows 64..127
    const int lcb  = (tid & 3) * 16;         // byte col 0/16/32/48
    const char* Ag = (const char*)(g_A + (size_t)m0 * KK2 + PHASE*Dc);
    const char* Bg = (const char*)(g_W + (size_t)n0 * KK2 + PHASE*Dc);

    const uint32_t aLoff = (uint32_t)((lane & 15) * (GP*2) + ((lane >> 4) * 8) * 2);
    const uint32_t bLoff = (uint32_t)(((lane & 7) + ((lane >> 4) & 1) * 8) * (GP*2)
                                      + (((lane >> 3) & 1) * 8) * 2);

    float acc[4][4][4];
    #pragma unroll
    for (int a = 0; a < 4; ++a)
        #pragma unroll
        for (int bn = 0; bn < 4; ++bn)
            #pragma unroll
            for (int c = 0; c < 4; ++c) acc[a][bn][c] = 0.f;

    auto stage_load = [&](int stg, int kt) {
        const uint32_t as = sbase + stg*GSTG;
        const uint32_t bs = as + STGB;
        const size_t gk = (size_t)kt * 64;   // byte offset of k-tile (32 bf16)
        cp16(as + ldr *80 + lcb, Ag + (size_t)ldr *(KK2*2) + gk + lcb);
        cp16(as + ldr2*80 + lcb, Ag + (size_t)ldr2*(KK2*2) + gk + lcb);
        cp16(bs + ldr *80 + lcb, Bg + (size_t)ldr *(KK2*2) + gk + lcb);
        cp16(bs + ldr2*80 + lcb, Bg + (size_t)ldr2*(KK2*2) + gk + lcb);
    };

    // prologue: loads for iters 0..NST-2
    #pragma unroll
    for (int s = 0; s < NST-1; ++s) { stage_load(s, s); CP_COMMIT(); }

    for (int it = 0; it < NIT; ++it) {
        cp_wait<NST-2>();
        __syncthreads();     // single barrier per iteration

        const int slot = it & (NST-1);
        const uint32_t as = sbase + slot*GSTG;
        const uint32_t bs = as + STGB;

        // ks=0 fragments first (so the cp.async below can't clobber anything live)
        uint32_t af[4][4], bf[4][2];
        #pragma unroll
        for (int mt = 0; mt < 4; ++mt)
            ldsm4(af[mt][0], af[mt][1], af[mt][2], af[mt][3],
                  as + (uint32_t)((wm*64 + mt*16)*(GP*2)) + aLoff);
        #pragma unroll
        for (int p2 = 0; p2 < 2; ++p2)
            ldsm4(bf[p2*2][0], bf[p2*2][1], bf[p2*2+1][0], bf[p2*2+1][1],
                  bs + (uint32_t)((wn*32 + p2*16)*(GP*2)) + bLoff);

        // issue load for iter it+NST-1 into slot (it-1)%NST (consumed last iter)
        if (it + NST-1 < NIT) stage_load((it + NST-1) & (NST-1), it + NST-1);
        CP_COMMIT();   // empty groups in tail keep wait-count semantics

        #pragma unroll
        for (int mt = 0; mt < 4; ++mt)
            #pragma unroll
            for (int nt = 0; nt < 4; ++nt)
                asm volatile(
                    "mma.sync.aligned.m16n8k16.row.col.f32.bf16.bf16.f32 "
                    "{%0,%1,%2,%3}, {%4,%5,%6,%7}, {%8,%9}, {%0,%1,%2,%3};"
                    : "+f"(acc[mt][nt][0]), "+f"(acc[mt][nt][1]),
                      "+f"(acc[mt][nt][2]), "+f"(acc[mt][nt][3])
                    : "r"(af[mt][0]), "r"(af[mt][1]), "r"(af[mt][2]), "r"(af[mt][3]),
                      "r"(bf[nt][0]), "r"(bf[nt][1]));

        // ks=1
        #pragma unroll
        for (int mt = 0; mt < 4; ++mt)
            ldsm4(af[mt][0], af[mt][1], af[mt][2], af[mt][3],
                  as + (uint32_t)((wm*64 + mt*16)*(GP*2) + 32) + aLoff);
        #pragma unroll
        for (int p2 = 0; p2 < 2; ++p2)
            ldsm4(bf[p2*2][0], bf[p2*2][1], bf[p2*2+1][0], bf[p2*2+1][1],
                  bs + (uint32_t)((wn*32 + p2*16)*(GP*2) + 32) + bLoff);
        #pragma unroll
        for (int mt = 0; mt < 4; ++mt)
            #pragma unroll
            for (int nt = 0; nt < 4; ++nt)
                asm volatile(
                    "mma.sync.aligned.m16n8k16.row.col.f32.bf16.bf16.f32 "
                    "{%0,%1,%2,%3}, {%4,%5,%6,%7}, {%8,%9}, {%0,%1,%2,%3};"
                    : "+f"(acc[mt][nt][0]), "+f"(acc[mt][nt][1]),
                      "+f"(acc[mt][nt][2]), "+f"(acc[mt][nt][3])
                    : "r"(af[mt][0]), "r"(af[mt][1]), "r"(af[mt][2]), "r"(af[mt][3]),
                      "r"(bf[nt][0]), "r"(bf[nt][1]));
    }

    // epilogue
    #pragma unroll
    for (int mt = 0; mt < 4; ++mt) {
        const int gm0 = m0 + wm*64 + mt*16 + grp;
        float rks0 = 0.f, rks1 = 0.f;
        if (PHASE == 0) { rks0 = g_rksum[gm0]; rks1 = g_rksum[gm0 + 8]; }
        #pragma unroll
        for (int nt = 0; nt < 4; ++nt) {
            const int gn = n0 + wn*32 + nt*8 + q*2;
            #pragma unroll
            for (int hh = 0; hh < 2; ++hh) {
                const int gm = gm0 + hh*8;
                const float rks = hh ? rks1 : rks0;
                const float c0 = acc[mt][nt][hh*2 + 0];
                const float c1 = acc[mt][nt][hh*2 + 1];
                const size_t o = (size_t)gm*Dc + gn;
                if (PHASE == 0) {
                    *reinterpret_cast<uint32_t*>(g_z + o) =
                        pack_bf16(c0 + rks, c1 + rks);
                } else {
                    const __nv_bfloat162 zh =
                        *reinterpret_cast<const __nv_bfloat162*>(g_z + o);
                    const float g0 = 1.f / (1.f + __expf(-(c0 + __bfloat162float(zh.x))));
                    const float g1 = 1.f / (1.f + __expf(-(c1 + __bfloat162float(zh.y))));
                    const float2 xv = *reinterpret_cast<const float2*>(x + o);
                    const float2 rv = *reinterpret_cast<const float2*>(g_routed + o);
                    float2 yv;
                    yv.x = xv.x + g0*rv.x;
                    yv.y = xv.y + g1*rv.y;
                    *reinterpret_cast<float2*>(g_y + o) = yv;
                }
            }
        }
    }
}

// ---------------- K5: LayerNorm over D ---------------------------------------
__global__ void k_ln(float* __restrict__ out, const float* __restrict__ gamma,
                     const float* __restrict__ beta) {
    const int m = blockIdx.x, t = threadIdx.x;     // 256 threads, 4 floats each
    const float4 v = reinterpret_cast<const float4*>(g_y + (size_t)m*Dc)[t];
    const int lane = t & 31, wid = t >> 5;
    __shared__ float red[16];

    float s = v.x + v.y + v.z + v.w;
    #pragma unroll
    for (int o = 16; o; o >>= 1) s += __shfl_xor_sync(0xffffffffu, s, o);
    if (lane == 0) red[wid] = s;
    __syncthreads();
    float mu = 0.f;
    #pragma unroll
    for (int i = 0; i < 8; ++i) mu += red[i];
    mu *= (1.f / Dc);

    const float d0 = v.x - mu, d1 = v.y - mu, d2 = v.z - mu, d3 = v.w - mu;
    float ss = d0*d0 + d1*d1 + d2*d2 + d3*d3;
    #pragma unroll
    for (int o = 16; o; o >>= 1) ss += __shfl_xor_sync(0xffffffffu, ss, o);
    if (lane == 0) red[8 + wid] = ss;
    __syncthreads();
    float var = 0.f;
    #pragma unroll
    for (int i = 0; i < 8; ++i) var += red[8 + i];
    var *= (1.f / Dc);
    const float inv = rsqrtf(var + 1e-5f);

    const float4 gm = reinterpret_cast<const float4*>(gamma)[t];
    const float4 bt = reinterpret_cast<const float4*>(beta)[t];
    float4 o4;
    o4.x = d0 * inv * gm.x + bt.x;
    o4.y = d1 * inv * gm.y + bt.y;
    o4.z = d2 * inv * gm.z + bt.z;
    o4.w = d3 * inv * gm.w + bt.w;
    reinterpret_cast<float4*>(out + (size_t)m*Dc)[t] = o4;
}

// ---------------- launch (R10-exact topology) --------------------------------
extern "C" void kernel_launch(void* const* d_in, const int* in_sizes, int n_in,
                              void* d_out, int out_size) {
    const float* x        = (const float*)d_in[0];
    const float* w_route  = (const float*)d_in[1];
    const float* conv_w0  = (const float*)d_in[2];
    const float* conv_w1  = (const float*)d_in[3];
    const float* w_gate   = (const float*)d_in[4];
    const float* ln_gamma = (const float*)d_in[5];
    const float* ln_beta  = (const float*)d_in[6];
    float* out = (float*)d_out;

    static cudaStream_t s1 = nullptr;
    static cudaEvent_t eFork = nullptr, eJoin = nullptr;
    if (s1 == nullptr) {
        cudaStreamCreateWithFlags(&s1, cudaStreamNonBlocking);
        cudaEventCreateWithFlags(&eFork, cudaEventDisableTiming);
        cudaEventCreateWithFlags(&eJoin, cudaEventDisableTiming);
        cudaFuncSetAttribute(k_gemm<0>, cudaFuncAttributeMaxDynamicSharedMemorySize, GSMEM);
        cudaFuncSetAttribute(k_gemm<1>, cudaFuncAttributeMaxDynamicSharedMemorySize, GSMEM);
    }

    k_route<<<Mc/128, 256>>>(x, w_route);

    // fork: sort + conv chain on side stream, overlapped with W-convert + GEMM phase 0
    cudaEventRecord(eFork, 0);
    cudaStreamWaitEvent(s1, eFork, 0);
    k_sort<<<dim3(2, Bc), 1024, 0, s1>>>();
    k_conv<0><<<dim3(Lc/64, Dc/256, Bc), 256, 0, s1>>>(x, conv_w0);
    k_conv<1><<<dim3(Lc/64, Dc/256, Bc), 256, 0, s1>>>(x, conv_w1);
    cudaEventRecord(eJoin, s1);

    k_wcvt<<<(Dc*(KK2/4))/256, 256>>>(w_gate);
    k_gemm<0><<<dim3(Dc/128, Mc/128), 256, GSMEM>>>(x);

    // join, then phase 1 + LN
    cudaStreamWaitEvent(0, eJoin, 0);
    k_gemm<1><<<dim3(Dc/128, Mc/128), 256, GSMEM>>>(x);
    k_ln<<<Mc, 256>>>(out, ln_gamma, ln_beta);
}